// round 4
// baseline (speedup 1.0000x reference)
#include <cuda_runtime.h>
#include <cstdint>

#define NUM_HEADS 8
#define IN_BITS   64
#define N_STATE   256
#define N_OUT     64
#define K_CONN    8
#define HASH      65536
#define BATCH     128
#define T_STEPS   128
#define TOTAL_IN  320   // IN_BITS + N_STATE

#define PACK_BLOCKS  16384           // pack: 16M floats / 128-per-warp / 8 warps
#define WPREC_SPLIT  4               // step-quarters per batch
#define WPREC_BLOCKS (BATCH * WPREC_SPLIT)

// Bit-packed threshold table: bit = (state_mem[n][a] >= 0.5). 2 MB, L2-resident.
__device__ uint32_t g_state_bits[N_STATE * (HASH / 32)];
// Precomputed window contributions: wacc[b][step][neuron] (lo + hi<<8). 16 MB.
__device__ uint32_t g_wacc[BATCH * T_STEPS * N_STATE];

#define PACK_LOHI(c, LO, HI)                                                    \
    LO = (uint32_t)((c).x & 255) | ((uint32_t)((c).y & 255) << 8)               \
       | ((uint32_t)((c).z & 255) << 16) | ((uint32_t)((c).w & 255) << 24);     \
    HI = (uint32_t)(((c).x >> 8) & 255) | ((uint32_t)(((c).y >> 8) & 255) << 8) \
       | ((uint32_t)(((c).z >> 8) & 255) << 16)                                 \
       | ((uint32_t)(((c).w >> 8) & 255) << 24);

// ---------------------------------------------------------------------------
// Fused prologue:
//   blocks [0, PACK_BLOCKS)              : bit-pack state_mem (HBM-bound)
//   blocks [PACK_BLOCKS, +WPREC_BLOCKS)  : window-contribution table (dp4a-bound)
// The two populations overlap: one saturates HBM, the other the fma pipe.
// ---------------------------------------------------------------------------
__global__ __launch_bounds__(256)
void fused_pre_kernel(const float* __restrict__ sm,
                      const int*   __restrict__ bits,
                      const int*   __restrict__ state_coeffs)
{
    __shared__ uint32_t ww[32 * 16];    // 32 windows expanded to bytes
    const int t = threadIdx.x;

    if (blockIdx.x < PACK_BLOCKS) {
        const int tid  = blockIdx.x * 256 + t;
        const int lane = t & 31;
        const int gw   = tid >> 5;
        const size_t base = (size_t)gw * 128;
        #pragma unroll
        for (int j = 0; j < 4; j++) {
            float v = sm[base + (size_t)j * 32 + lane];
            uint32_t b = __ballot_sync(0xFFFFFFFFu, v >= 0.5f);
            if (lane == 0) g_state_bits[gw * 4 + j] = b;
        }
        return;
    }

    // ---- window precompute: block -> (batch b, step-quarter q) ----
    const int blk = blockIdx.x - PACK_BLOCKS;
    const int b   = blk >> 2;
    const int q   = blk & 3;

    const int4* bits4 = reinterpret_cast<const int4*>(
        bits + (size_t)b * (T_STEPS * IN_BITS)) + q * 32 * 16;
    for (int w = t; w < 32 * 16; w += 256) {
        int4 v = bits4[w];
        ww[w] = (uint32_t)(v.x & 1) | ((uint32_t)(v.y & 1) << 8)
              | ((uint32_t)(v.z & 1) << 16) | ((uint32_t)(v.w & 1) << 24);
    }

    uint32_t wlo[16], whi[16];
    {
        const int4* crow = reinterpret_cast<const int4*>(state_coeffs + (size_t)t * TOTAL_IN);
        #pragma unroll
        for (int k = 0; k < 16; k++) { int4 c = crow[k]; PACK_LOHI(c, wlo[k], whi[k]); }
    }
    __syncthreads();

    uint32_t* dst = g_wacc + ((size_t)b << 15) + ((q * 32) << 8) + t;
    for (int s = 0; s < 32; s++) {
        const uint4* xv = reinterpret_cast<const uint4*>(ww + s * 16);
        uint32_t l0 = 0, h0 = 0, l1 = 0, h1 = 0;
        #pragma unroll
        for (int k = 0; k < 4; k += 2) {
            uint4 x0 = xv[k], x1 = xv[k + 1];
            l0 = __dp4a(x0.x, wlo[k*4+0], l0); h0 = __dp4a(x0.x, whi[k*4+0], h0);
            l0 = __dp4a(x0.y, wlo[k*4+1], l0); h0 = __dp4a(x0.y, whi[k*4+1], h0);
            l0 = __dp4a(x0.z, wlo[k*4+2], l0); h0 = __dp4a(x0.z, whi[k*4+2], h0);
            l0 = __dp4a(x0.w, wlo[k*4+3], l0); h0 = __dp4a(x0.w, whi[k*4+3], h0);
            l1 = __dp4a(x1.x, wlo[k*4+4], l1); h1 = __dp4a(x1.x, whi[k*4+4], h1);
            l1 = __dp4a(x1.y, wlo[k*4+5], l1); h1 = __dp4a(x1.y, whi[k*4+5], h1);
            l1 = __dp4a(x1.z, wlo[k*4+6], l1); h1 = __dp4a(x1.z, whi[k*4+6], h1);
            l1 = __dp4a(x1.w, wlo[k*4+7], l1); h1 = __dp4a(x1.w, whi[k*4+7], h1);
        }
        dst[s << 8] = (l0 + l1) + ((h0 + h1) << 8);
    }
}

// ---------------------------------------------------------------------------
// Main scan. One CTA per batch, 256 threads, thread t = neuron t.
// Per step: 128 state dp4a (8 chains) + prefetched wacc + 1 L2 gather + 1 bar.
// wacc for step s+1 is LDG'd during step s (independent of state -> hidden).
// ---------------------------------------------------------------------------
__global__ __launch_bounds__(256, 1)
void ram_scan_kernel(const int*   __restrict__ bits,          // (B, T*64)
                     const int*   __restrict__ state_coeffs,  // (256, 320)
                     const int*   __restrict__ head_conn,     // (8, 64, 8)
                     const int*   __restrict__ head_coeffs,   // (8, 64, 8)
                     const float* __restrict__ head_mem,      // (8, 64, 65536)
                     float*       __restrict__ out)           // (B, 64)
{
    __shared__ uint32_t stbuf[2][64];            // double-buffered 256-byte state

    const int b = blockIdx.x;
    const int t = threadIdx.x;                   // neuron id

    // ---- state-part coefficients (words 16..79 of the row) into registers ----
    uint32_t clo[64], chi[64];
    {
        const int4* crow = reinterpret_cast<const int4*>(state_coeffs + (size_t)t * TOTAL_IN);
        #pragma unroll
        for (int k = 0; k < 64; k++) { int4 c = crow[16 + k]; PACK_LOHI(c, clo[k], chi[k]); }
    }
    if (t < 64) stbuf[0][t] = 0u;   // initial state = 0

    const uint32_t* prow = g_state_bits + ((size_t)t << 11);   // 2048 words/row
    const uint32_t* wtab = g_wacc + ((size_t)b << 15);         // [step][neuron]

    uint32_t wacc = wtab[t];                                   // step 0, prefetched
    __syncthreads();

    #pragma unroll 2
    for (int step = 0; step < T_STEPS; step++) {
        const int cur = step & 1, nxt = cur ^ 1;
        const uint4* st4 = reinterpret_cast<const uint4*>(stbuf[cur]);

        // state dot: 256 bytes, 128 dp4a in 8 chains of 16
        uint32_t al[4] = {0u,0u,0u,0u}, ah[4] = {0u,0u,0u,0u};
        #pragma unroll
        for (int k = 0; k < 16; k++) {
            uint4 x = st4[k];
            const int c = k & 3;
            al[c] = __dp4a(x.x, clo[k*4+0], al[c]); ah[c] = __dp4a(x.x, chi[k*4+0], ah[c]);
            al[c] = __dp4a(x.y, clo[k*4+1], al[c]); ah[c] = __dp4a(x.y, chi[k*4+1], ah[c]);
            al[c] = __dp4a(x.z, clo[k*4+2], al[c]); ah[c] = __dp4a(x.z, chi[k*4+2], ah[c]);
            al[c] = __dp4a(x.w, clo[k*4+3], al[c]); ah[c] = __dp4a(x.w, chi[k*4+3], ah[c]);
        }
        const uint32_t s    = (al[0]+al[1]+al[2]+al[3])
                            + ((ah[0]+ah[1]+ah[2]+ah[3]) << 8) + wacc;
        const uint32_t addr = s & 0xFFFFu;

        // random gather (L2-resident 2 MB table)
        const uint32_t wword = prow[addr >> 5];

        // prefetch next step's window contribution (independent -> hidden)
        const uint32_t wnext = wtab[(((step + 1) & (T_STEPS - 1)) << 8) + t];

        reinterpret_cast<uint8_t*>(stbuf[nxt])[t] =
            (uint8_t)((wword >> (addr & 31u)) & 1u);
        __syncthreads();   // new state visible; old buffer free
        wacc = wnext;
    }

    // ---- Head readout (threads 0..63); final state in stbuf[0] (T even) ----
    if (t < N_OUT) {
        const uint8_t* state_b = reinterpret_cast<const uint8_t*>(stbuf[0]);
        const int* lw = bits + (size_t)b * (T_STEPS * IN_BITS) + (T_STEPS * IN_BITS - 3);
        int hidx = (lw[0] << 2) + (lw[1] << 1) + lw[2];          // 0..7
        const int o = t;
        const int base = (hidx * N_OUT + o) * K_CONN;
        uint32_t addr = 0u;
        #pragma unroll
        for (int k = 0; k < K_CONN; k++) {
            int conn = __ldg(head_conn + base + k);
            uint32_t c = (uint32_t)__ldg(head_coeffs + base + k);
            addr += state_b[conn] ? c : 0u;
        }
        addr &= 0xFFFFu;
        out[(size_t)b * N_OUT + o] =
            __ldg(head_mem + (((size_t)(hidx * N_OUT + o)) << 16) + addr);
    }
}

extern "C" void kernel_launch(void* const* d_in, const int* in_sizes, int n_in,
                              void* d_out, int out_size)
{
    const int*   bits         = (const int*)  d_in[0];
    const int*   state_coeffs = (const int*)  d_in[1];
    const float* state_mem    = (const float*)d_in[2];
    const int*   head_conn    = (const int*)  d_in[3];
    const int*   head_coeffs  = (const int*)  d_in[4];
    const float* head_mem     = (const float*)d_in[5];
    float*       out          = (float*)      d_out;

    fused_pre_kernel<<<PACK_BLOCKS + WPREC_BLOCKS, 256>>>(state_mem, bits, state_coeffs);
    ram_scan_kernel<<<BATCH, 256>>>(bits, state_coeffs,
                                    head_conn, head_coeffs, head_mem, out);
}